// round 10
// baseline (speedup 1.0000x reference)
#include <cuda_runtime.h>

#define BATCH 64
#define NN 512
#define NDIAG 1023
#define NEGV  (-1e30f)
#define INV_LN2 1.44269504088896340736f
#define LN2F    0.69314718055994530942f
#define CADDR (1022 * NN + 511)

// Diagonal-major layout: (k, i) -> k*NN + i, valid i in [max(0,k-511), min(511,k)].
__device__ float g_ddiag[(size_t)BATCH * NDIAG * NN];  // D / ln2
__device__ float g_f[(size_t)BATCH * NDIAG * NN];      // forward DP (log2 domain)
__device__ float g_b[(size_t)BATCH * NDIAG * NN];      // backward DP MINUS d (log2)
__device__ float g_max;                                // global logit max (log2)

__device__ __forceinline__ float ex2f(float x) {
    float y; asm("ex2.approx.ftz.f32 %0, %1;" : "=f"(y) : "f"(x)); return y;
}
__device__ __forceinline__ float lg2f(float x) {
    float y; asm("lg2.approx.ftz.f32 %0, %1;" : "=f"(y) : "f"(x)); return y;
}

// ---------------------------------------------------------------------------
// Pre-pass: D (row-major) -> g_ddiag (diag-major), scaled by 1/ln2.
// ---------------------------------------------------------------------------
__global__ void __launch_bounds__(256) diagize_kernel(const float* __restrict__ D) {
    __shared__ float t[32][34];
    int b = blockIdx.z, i0 = blockIdx.y * 32, j0 = blockIdx.x * 32;
    const float* Db = D + (size_t)b * NN * NN;
    float* out = g_ddiag + (size_t)b * NDIAG * NN;
    int tid = threadIdx.x, lane = tid & 31, w = tid >> 5;
#pragma unroll
    for (int r = 0; r < 4; r++) {
        int il = w + 8 * r;
        t[il][lane] = Db[(size_t)(i0 + il) * NN + j0 + lane] * INV_LN2;
    }
    __syncthreads();
#pragma unroll
    for (int r = 0; r < 8; r++) {
        int ld = w + 8 * r;
        if (ld < 63) {
            int ilo = max(0, ld - 31);
            int il = ilo + lane;
            if (il <= min(31, ld)) {
                int k = i0 + j0 + ld;
                out[(size_t)k * NN + (i0 + il)] = t[il][ld - il];
            }
        }
    }
}

__device__ __forceinline__ float lse_cell(float dg, float up, float lf, float dcur) {
    float hi1 = fmaxf(dg, up);
    float lo1 = fminf(dg, up);
    float m   = fmaxf(hi1, lf);
    float o2  = fminf(hi1, lf);
    float s = ex2f(lo1 - m) + ex2f(o2 - m);   // third term is 2^0 = 1
    return dcur + m + lg2f(1.0f + s);
}

// ---------------------------------------------------------------------------
// Wavefront DP, TWO diagonals per __syncthreads via redundant compute.
// One CTA per (batch, direction), 512 threads = one row each.
// Phase ph computes diags ka=2ph, kb=ka+1. From smem (diags ka-1, ka-2 in
// rotating buffers, 2-slot NEG boundary at [0..1]):
//   vA  = cell(i,   ka)  and  vAm = cell(i-1, ka)   (redundant, pure SIMD)
//   vB  = cell(i,   kb)  from vA/vAm in registers — no communication.
// Barrier count halves; the LDS->LSE chain amortizes over 2 diagonals.
// D prefetch: stream pf[8] (rows i) + pfm[4] (rows i-1, clamped), 8 diags deep.
// Backward CTAs write (val - d) so combine never re-reads d.
// ---------------------------------------------------------------------------
__global__ void __launch_bounds__(512) dp_kernel() {
    __shared__ float bufs[4][NN + 2];   // [rot][2 + i]; slots 0,1 = boundaries
    int bx = blockIdx.x;
    int b = bx >> 1, dir = bx & 1;
    const float* dd = g_ddiag + (size_t)b * NDIAG * NN;
    float* out = (dir ? g_b : g_f) + (size_t)b * NDIAG * NN;

    int i = threadIdx.x;
    int im = max(i - 1, 0);
#pragma unroll
    for (int r = 0; r < 4; r++) {
        bufs[r][i] = NEGV;
        if (i < 2) bufs[r][NN + i] = NEGV;
    }
    __syncthreads();

    // prefetch streams
    float pf[8], pfm[4];
#pragma unroll
    for (int q = 0; q < 8; q++) {
        int a = q * NN + i;
        pf[q] = dd[dir ? (CADDR - a) : a];
    }
#pragma unroll
    for (int q = 0; q < 4; q++) {
        int a = 2 * q * NN + im;
        pfm[q] = dd[dir ? (CADDR - a) : a];
    }

    for (int t = 0; t < 128; t++) {
#pragma unroll
        for (int pp = 0; pp < 4; pp++) {
            int ka = t * 8 + 2 * pp;           // ka: 0..1022 even, kb = ka+1
            float dA  = pf[2 * pp];
            float dB  = pf[2 * pp + 1];
            float dAm = pfm[pp];
            {   // prefetch 8 diagonals ahead (4 phases)
                int kA = min(ka + 8, 1022);
                int kB = min(ka + 9, 1022);
                int aA = kA * NN + i, aB = kB * NN + i, aM = kA * NN + im;
                pf[2 * pp]     = dd[dir ? (CADDR - aA) : aA];
                pf[2 * pp + 1] = dd[dir ? (CADDR - aB) : aB];
                pfm[pp]        = dd[dir ? (CADDR - aM) : aM];
            }
            const float* p1 = bufs[(pp & 1) ? 3 : 1];   // diag ka-1
            const float* p2 = bufs[(pp & 1) ? 2 : 0];   // diag ka-2
            float* bufA = bufs[(pp & 1) ? 0 : 2];       // diag ka
            float* bufB = bufs[(pp & 1) ? 1 : 3];       // diag kb

            float p1_i  = p1[2 + i];
            float p1_i1 = p1[1 + i];
            float p1_i2 = p1[i];
            float p2_i1 = p2[1 + i];
            float p2_i2 = p2[i];

            int ja = ka - i;                   // vA: cell (i, ja)
            float dgA = (ja == 0) ? ((i == 0) ? 0.0f : NEGV) : p2_i1;
            float lfA = (ja == 0) ? NEGV : p1_i;
            float vA  = lse_cell(dgA, p1_i1, lfA, dA);
            bool validA = (ja >= 0) && (ja < NN);
            vA = validA ? vA : NEGV;

            int jam = ja + 1;                  // vAm: cell (i-1, jam)
            float dgAm = (jam == 0) ? ((i == 1) ? 0.0f : NEGV) : p2_i2;
            float lfAm = (jam == 0) ? NEGV : p1_i1;
            float vAm  = lse_cell(dgAm, p1_i2, lfAm, dAm);
            vAm = ((jam >= 0) && (jam < NN) && (i >= 1)) ? vAm : NEGV;

            int jb = ja + 1;                   // vB: cell (i, jb) on diag kb
            float dgB = (jb == 0) ? ((i == 0) ? 0.0f : NEGV) : p1_i1;
            float lfB = (jb == 0) ? NEGV : vA;
            float upB = (i == 0) ? NEGV : vAm;
            float vB  = lse_cell(dgB, upB, lfB, dB);
            bool validB = (jb >= 0) && (jb < NN) && (ka + 1 < NDIAG);
            vB = validB ? vB : NEGV;

            bufA[2 + i] = vA;
            bufB[2 + i] = vB;
            if (validA) out[(size_t)ka * NN + i] = dir ? (vA - dA) : vA;
            if (validB) out[(size_t)(ka + 1) * NN + i] = dir ? (vB - dB) : vB;
            __syncthreads();
        }
    }
}

// ---------------------------------------------------------------------------
// Global max: every path passes through the corner cell, so
// max logit = f(N-1, M-1) maximized over batches.
// ---------------------------------------------------------------------------
__global__ void max_kernel() {
    int t = threadIdx.x;   // 32 threads
    float m = -3.4e38f;
    for (int b = t; b < BATCH; b += 32)
        m = fmaxf(m, g_f[(size_t)b * NDIAG * NN + (size_t)1022 * NN + 511]);
#pragma unroll
    for (int o = 16; o > 0; o >>= 1)
        m = fmaxf(m, __shfl_xor_sync(0xffffffffu, m, o));
    if (t == 0) g_max = m;
}

// ---------------------------------------------------------------------------
// Combine + finish fused: out = (f2 + (b2-d2) - max2) * ln2, de-diagonalized
// to row-major via a padded smem tile.
// ---------------------------------------------------------------------------
__global__ void __launch_bounds__(256) combine_kernel(float* __restrict__ out) {
    __shared__ float tile[32][257];
    int b = blockIdx.y;
    int k0 = blockIdx.x * 32;
    const float* fd = g_f + (size_t)b * NDIAG * NN;
    const float* bd = g_b + (size_t)b * NDIAG * NN;
    float* ob = out + (size_t)b * NN * NN;
    int tid = threadIdx.x, lane = tid & 31, w = tid >> 5;
    float mx = g_max;

    for (int ih = 0; ih < 2; ih++) {
        int ibase = ih * 256;
        for (int kk = 0; kk < 32; kk++) {
            int k = k0 + kk;
            int i = ibase + tid;
            int j = k - i;
            float v = 0.0f;
            if (j >= 0 && j < NN) {
                int a = k * NN + i;
                v = (fd[a] + bd[(1022 - k) * NN + (511 - i)] - mx) * LN2F;
            }
            tile[kk][tid] = v;
        }
        __syncthreads();
        for (int rr = 0; rr < 32; rr++) {
            int i = ibase + w * 32 + rr;
            int jlo = max(0, k0 - i);
            int jhi = min(NN - 1, k0 + 31 - i);
            int j = jlo + lane;
            if (j <= jhi) {
                int kk = i + j - k0;
                ob[(size_t)i * NN + j] = tile[kk][i - ibase];
            }
        }
        __syncthreads();
    }
}

extern "C" void kernel_launch(void* const* d_in, const int* in_sizes, int n_in,
                              void* d_out, int out_size) {
    const float* d = (const float*)d_in[0];
    float* out = (float*)d_out;

    dim3 dgrid(16, 16, BATCH);
    diagize_kernel<<<dgrid, 256>>>(d);

    dp_kernel<<<BATCH * 2, 512>>>();

    max_kernel<<<1, 32>>>();

    dim3 cgrid(32, BATCH);
    combine_kernel<<<cgrid, 256>>>(out);
}

// round 11
// speedup vs baseline: 1.2445x; 1.2445x over previous
#include <cuda_runtime.h>

#define BATCH 64
#define NN 512
#define NDIAG 1023
#define NEGV  (-1e30f)
#define INV_LN2 1.44269504088896340736f
#define LN2F    0.69314718055994530942f
#define CADDR (1022 * NN + 511)

// Diagonal-major layout: (k, i) -> k*NN + i, valid i in [max(0,k-511), min(511,k)].
__device__ float g_ddiag[(size_t)BATCH * NDIAG * NN];  // D / ln2
__device__ float g_f[(size_t)BATCH * NDIAG * NN];      // forward DP (log2 domain)
__device__ float g_b[(size_t)BATCH * NDIAG * NN];      // backward DP MINUS d (log2)
__device__ float g_max;                                // global logit max (log2)

__device__ __forceinline__ float ex2f(float x) {
    float y; asm("ex2.approx.ftz.f32 %0, %1;" : "=f"(y) : "f"(x)); return y;
}
__device__ __forceinline__ float lg2f(float x) {
    float y; asm("lg2.approx.ftz.f32 %0, %1;" : "=f"(y) : "f"(x)); return y;
}

// ---------------------------------------------------------------------------
// Pre-pass: D (row-major) -> g_ddiag (diag-major), scaled by 1/ln2.
// ---------------------------------------------------------------------------
__global__ void __launch_bounds__(256) diagize_kernel(const float* __restrict__ D) {
    __shared__ float t[32][34];
    int b = blockIdx.z, i0 = blockIdx.y * 32, j0 = blockIdx.x * 32;
    const float* Db = D + (size_t)b * NN * NN;
    float* out = g_ddiag + (size_t)b * NDIAG * NN;
    int tid = threadIdx.x, lane = tid & 31, w = tid >> 5;
#pragma unroll
    for (int r = 0; r < 4; r++) {
        int il = w + 8 * r;
        t[il][lane] = Db[(size_t)(i0 + il) * NN + j0 + lane] * INV_LN2;
    }
    __syncthreads();
#pragma unroll
    for (int r = 0; r < 8; r++) {
        int ld = w + 8 * r;
        if (ld < 63) {
            int ilo = max(0, ld - 31);
            int il = ilo + lane;
            if (il <= min(31, ld)) {
                int k = i0 + j0 + ld;
                out[(size_t)k * NN + (i0 + il)] = t[il][ld - il];
            }
        }
    }
}

__device__ __forceinline__ float lse_cell(float dg, float up, float lf, float dcur) {
    float hi1 = fmaxf(dg, up);
    float lo1 = fminf(dg, up);
    float m   = fmaxf(hi1, lf);
    float o2  = fminf(hi1, lf);
    float s = ex2f(lo1 - m) + ex2f(o2 - m);   // third term is 2^0 = 1
    return dcur + m + lg2f(1.0f + s);
}

// float2 of D for rows (2t, 2t+1) on diag k. Backward reads the mirrored
// addresses (descending) -> components come back swapped (y = even row).
template<bool BWD>
__device__ __forceinline__ float2 ld2(const float* dd, int k, int iE) {
    if (!BWD) return *(const float2*)(dd + (size_t)k * NN + iE);
    return *(const float2*)(dd + (size_t)(CADDR - 1) - ((size_t)k * NN + iE));
}

// ---------------------------------------------------------------------------
// Wavefront DP: 256 threads, thread t owns rows (2t, 2t+1). Odd-row cell uses
// register inputs only; even-row cell needs 2 LDS from the neighbor thread's
// published odd-row values (diags k-1, k-2). One STS (odd value) per thread
// per diagonal. 4 rotating smem buffers (static selectors), k-loop unrolled
// x8 with the proven 8-deep float2 LDG prefetch. One CTA per (batch, dir).
// Backward CTAs write (val - d) so combine never re-reads d.
// ---------------------------------------------------------------------------
template<bool BWD>
__device__ __forceinline__ void dp_impl(int b, float (*bufs)[258]) {
    const float* dd = g_ddiag + (size_t)b * NDIAG * NN;
    float* out = (BWD ? g_b : g_f) + (size_t)b * NDIAG * NN;
    int t = threadIdx.x;
    int iE = 2 * t;                  // even row; odd row = iE + 1

    float2 pf[8];
#pragma unroll
    for (int q = 0; q < 8; q++) pf[q] = ld2<BWD>(dd, q, iE);

    float vE1 = NEGV, vE2 = NEGV;    // even row at diag k-1, k-2
    float vO1 = NEGV, vO2 = NEGV;    // odd  row at diag k-1, k-2

    for (int tt = 0; tt < 128; tt++) {
#pragma unroll
        for (int p = 0; p < 8; p++) {
            int k = tt * 8 + p;                   // k==1023 is a no-op pad
            float2 dc = pf[p];
            {
                int kn = k + 8; if (kn > NDIAG - 1) kn = NDIAG - 1;
                pf[p] = ld2<BWD>(dd, kn, iE);
            }
            if (k < NDIAG) {                      // uniform over the block
                float* bc        = bufs[p & 3];          // diag k
                const float* b1p = bufs[(p + 3) & 3];    // diag k-1
                const float* b2p = bufs[(p + 2) & 3];    // diag k-2
                float dE = BWD ? dc.y : dc.x;
                float dO = BWD ? dc.x : dc.y;

                float nb1 = b1p[1 + t];   // v(iE-1, k-1)  (t=0 -> NEG slot)
                float nb2 = b2p[1 + t];   // v(iE-1, k-2)

                int jE = k - iE;
                int jO = jE - 1;

                // even cell (iE, jE): up=nb1, dg=nb2, lf=vE1
                float dgE = (jE == 0) ? ((iE == 0) ? 0.0f : NEGV) : nb2;
                float lfE = (jE == 0) ? NEGV : vE1;
                float vE  = lse_cell(dgE, nb1, lfE, dE);
                vE = (jE >= 0 && jE < NN) ? vE : NEGV;

                // odd cell (iE+1, jO): up=vE1, dg=vE2, lf=vO1 (all registers)
                float dgO = (jO == 0) ? NEGV : vE2;
                float lfO = (jO == 0) ? NEGV : vO1;
                float vO  = lse_cell(dgO, vE1, lfO, dO);
                vO = (jO >= 0 && jO < NN) ? vO : NEGV;

                bc[2 + t] = vO;                   // publish odd-row value
                if (k >= iE && k <= iE + NN) {    // either row in range
                    float2 st;
                    st.x = BWD ? (vE - dE) : vE;
                    st.y = BWD ? (vO - dO) : vO;
                    *(float2*)(out + (size_t)k * NN + iE) = st;
                }
                vE2 = vE1; vE1 = vE;
                vO2 = vO1; vO1 = vO;
                __syncthreads();
            }
        }
    }
}

__global__ void __launch_bounds__(256) dp_kernel() {
    __shared__ float bufs[4][258];   // [rot][2 + t]; slots 0,1 = boundary NEG
    int bx = blockIdx.x;
    int b = bx >> 1, dir = bx & 1;
    float* bp = &bufs[0][0];
    for (int q = threadIdx.x; q < 4 * 258; q += 256) bp[q] = NEGV;
    __syncthreads();
    if (dir) dp_impl<true>(b, bufs);
    else     dp_impl<false>(b, bufs);
}

// ---------------------------------------------------------------------------
// Global max: every path passes through the corner cell, so
// max logit = f(N-1, M-1) maximized over batches.
// ---------------------------------------------------------------------------
__global__ void max_kernel() {
    int t = threadIdx.x;   // 32 threads
    float m = -3.4e38f;
    for (int b = t; b < BATCH; b += 32)
        m = fmaxf(m, g_f[(size_t)b * NDIAG * NN + (size_t)1022 * NN + 511]);
#pragma unroll
    for (int o = 16; o > 0; o >>= 1)
        m = fmaxf(m, __shfl_xor_sync(0xffffffffu, m, o));
    if (t == 0) g_max = m;
}

// ---------------------------------------------------------------------------
// Combine + finish fused: out = (f2 + (b2-d2) - max2) * ln2, de-diagonalized
// to row-major via a padded smem tile.
// ---------------------------------------------------------------------------
__global__ void __launch_bounds__(256) combine_kernel(float* __restrict__ out) {
    __shared__ float tile[32][257];
    int b = blockIdx.y;
    int k0 = blockIdx.x * 32;
    const float* fd = g_f + (size_t)b * NDIAG * NN;
    const float* bd = g_b + (size_t)b * NDIAG * NN;
    float* ob = out + (size_t)b * NN * NN;
    int tid = threadIdx.x, lane = tid & 31, w = tid >> 5;
    float mx = g_max;

    for (int ih = 0; ih < 2; ih++) {
        int ibase = ih * 256;
        for (int kk = 0; kk < 32; kk++) {
            int k = k0 + kk;
            int i = ibase + tid;
            int j = k - i;
            float v = 0.0f;
            if (j >= 0 && j < NN) {
                int a = k * NN + i;
                v = (fd[a] + bd[(1022 - k) * NN + (511 - i)] - mx) * LN2F;
            }
            tile[kk][tid] = v;
        }
        __syncthreads();
        for (int rr = 0; rr < 32; rr++) {
            int i = ibase + w * 32 + rr;
            int jlo = max(0, k0 - i);
            int jhi = min(NN - 1, k0 + 31 - i);
            int j = jlo + lane;
            if (j <= jhi) {
                int kk = i + j - k0;
                ob[(size_t)i * NN + j] = tile[kk][i - ibase];
            }
        }
        __syncthreads();
    }
}

extern "C" void kernel_launch(void* const* d_in, const int* in_sizes, int n_in,
                              void* d_out, int out_size) {
    const float* d = (const float*)d_in[0];
    float* out = (float*)d_out;

    dim3 dgrid(16, 16, BATCH);
    diagize_kernel<<<dgrid, 256>>>(d);

    dp_kernel<<<BATCH * 2, 256>>>();

    max_kernel<<<1, 32>>>();

    dim3 cgrid(32, BATCH);
    combine_kernel<<<cgrid, 256>>>(out);
}